// round 8
// baseline (speedup 1.0000x reference)
#include <cuda_runtime.h>

#define NMAX 100000
#define EMAX 1600000
#define DD   128

typedef unsigned long long ull;

// ---------------- device scratch (symbol-only access, no allocations) -----
__device__ __align__(16) float g_t[(size_t)NMAX * DD];   // h @ W_l^T
__device__ __align__(16) float g_z[(size_t)NMAX * DD];   // h @ W_r^T + b
__device__ __align__(16) float g_h[(size_t)NMAX * DD];   // layer activations
__device__ int   g_rowptr[NMAX + 1];
__device__ int   g_cursor[NMAX];
__device__ int   g_col[EMAX];
__device__ float g_inv[NMAX];
__device__ int   g_cnt[NMAX];
__device__ int   g_bsum[1024];
__device__ int   g_boff[1024];
__device__ int   g_wide;   // 1 if edge_index is int64-layout, 0 if int32

// packed f32x2 helpers
#define FMA2(d, a, b) asm("fma.rn.f32x2 %0, %1, %2, %3;" : "=l"(d) : "l"(a), "l"(b), "l"(d))
#define ADD2(d, a, b) asm("add.rn.f32x2 %0, %1, %2;"     : "=l"(d) : "l"(a), "l"(b))

__device__ __forceinline__ ull pack2(float lo, float hi) {
    ull r; asm("mov.b64 %0, {%1, %2};" : "=l"(r) : "f"(lo), "f"(hi)); return r;
}

// ---------------- copies (param -> symbol) --------------------------------
__global__ void copy_in_kernel(const float4* __restrict__ x, int n4) {
    int i = blockIdx.x * blockDim.x + threadIdx.x;
    if (i < n4) ((float4*)g_h)[i] = x[i];
}

// ---------------- edge dtype detection ------------------------------------
__global__ void detect_kernel(const int* __restrict__ ei, int E) {
    __shared__ int s_or;
    if (threadIdx.x == 0) s_or = 0;
    __syncthreads();
    int acc = 0;
    for (int i = blockIdx.x * blockDim.x + threadIdx.x; i < E; i += gridDim.x * blockDim.x)
        acc |= ei[2 * i + 1];
    if (acc) atomicOr(&s_or, 1);
    __syncthreads();
    if (threadIdx.x == 0 && s_or) g_wide = 0;
}

__global__ void init_flag_kernel() { g_wide = 1; }

// ---------------- CSR build ----------------
__global__ void zero_cnt_kernel(int n) {
    int i = blockIdx.x * blockDim.x + threadIdx.x;
    if (i < n) g_cnt[i] = 0;
}

__global__ void hist_kernel(const int* __restrict__ ei, int E) {
    int e = blockIdx.x * blockDim.x + threadIdx.x;
    if (e < E) {
        int dst = g_wide ? ei[2 * ((size_t)E + e)] : ei[(size_t)E + e];
        atomicAdd(&g_cnt[dst], 1);
    }
}

// 3-phase scan: block-reduce, scan partials, local scan + offset.
__global__ void scan1_kernel(int n) {
    __shared__ int sh[256];
    int i = blockIdx.x * 256 + threadIdx.x;
    sh[threadIdx.x] = (i < n) ? g_cnt[i] : 0;
    __syncthreads();
    for (int off = 128; off > 0; off >>= 1) {
        if (threadIdx.x < off) sh[threadIdx.x] += sh[threadIdx.x + off];
        __syncthreads();
    }
    if (threadIdx.x == 0) g_bsum[blockIdx.x] = sh[0];
}

__global__ void scan2_kernel(int nb) {
    __shared__ int sh[1024];
    int t = threadIdx.x;
    int v = (t < nb) ? g_bsum[t] : 0;
    sh[t] = v;
    __syncthreads();
    for (int off = 1; off < 1024; off <<= 1) {
        int u = (t >= off) ? sh[t - off] : 0;
        __syncthreads();
        sh[t] += u;
        __syncthreads();
    }
    if (t < nb) g_boff[t] = sh[t] - v;   // exclusive
}

__global__ void scan3_kernel(int n) {
    __shared__ int sh[256];
    int i = blockIdx.x * 256 + threadIdx.x;
    int v = (i < n) ? g_cnt[i] : 0;
    sh[threadIdx.x] = v;
    __syncthreads();
    for (int off = 1; off < 256; off <<= 1) {
        int u = ((int)threadIdx.x >= off) ? sh[threadIdx.x - off] : 0;
        __syncthreads();
        sh[threadIdx.x] += u;
        __syncthreads();
    }
    if (i < n) {
        int incl = sh[threadIdx.x] + g_boff[blockIdx.x];
        g_rowptr[i + 1] = incl;
        g_cursor[i]     = incl - v;
        g_inv[i]        = 1.0f / fmaxf((float)v, 1.0f);
    }
    if (blockIdx.x == 0 && threadIdx.x == 0) g_rowptr[0] = 0;
}

__global__ void fill_kernel(const int* __restrict__ ei, int E) {
    int e = blockIdx.x * blockDim.x + threadIdx.x;
    if (e < E) {
        int wide = g_wide;
        int src = wide ? ei[2 * (size_t)e]        : ei[e];
        int dst = wide ? ei[2 * ((size_t)E + e)]  : ei[(size_t)E + e];
        int pos = atomicAdd(&g_cursor[dst], 1);
        g_col[pos] = src;
    }
}

// ---------------- dual GEMM via packed f32x2 FMA --------------------------
// g_t = g_h@Wl^T ; g_z = g_h@Wr^T + b.  Tile 64 rows x 64 cols, grid.y = half.
// A staged duplicated ({a,a} per elem, 16KB), W staged transposed [k][n] (8KB x2).
// Thread (tx,ty): col pair (2tx, 2tx+1), rows ty*8..ty*8+7.
__global__ __launch_bounds__(256)
void gemm_dual_kernel(const float* __restrict__ Wl,
                      const float* __restrict__ Wr,
                      const float* __restrict__ bias,
                      int n)
{
    __shared__ ull   As2[64 * 32];    // [row][k] duplicated pairs, 16 KB
    __shared__ float Wlt[32][64];     // [k][n], 8 KB
    __shared__ float Wrt[32][64];

    const int tid = threadIdx.x;
    const int tx = tid & 31;          // col-pair index
    const int ty = tid >> 5;          // row group (8 rows)
    const int row0 = blockIdx.x * 64;
    const int ncol0 = blockIdx.y * 64;

    ull accl[8], accr[8];
    #pragma unroll
    for (int i = 0; i < 8; i++) { accl[i] = 0ull; accr[i] = 0ull; }

    for (int kc = 0; kc < 4; kc++) {
        // stage A chunk: 64 rows x 8 float4, duplicated into pairs
        #pragma unroll
        for (int l = 0; l < 2; l++) {
            int i = tid + l * 256;
            int r = i >> 3, c4 = i & 7;
            float4 v = make_float4(0.f, 0.f, 0.f, 0.f);
            if (row0 + r < n)
                v = ((const float4*)g_h)[(size_t)(row0 + r) * 32 + kc * 8 + c4];
            ull* dst = &As2[r * 32 + c4 * 4];
            dst[0] = pack2(v.x, v.x);
            dst[1] = pack2(v.y, v.y);
            dst[2] = pack2(v.z, v.z);
            dst[3] = pack2(v.w, v.w);
        }
        // stage W chunk transposed: 64 n-rows x 8 float4 each
        #pragma unroll
        for (int l = 0; l < 2; l++) {
            int i = tid + l * 256;
            int nr = i & 63, k4 = i >> 6;    // k4 0..7
            float4 vl = ((const float4*)Wl)[(ncol0 + nr) * 32 + kc * 8 + k4];
            float4 vr = ((const float4*)Wr)[(ncol0 + nr) * 32 + kc * 8 + k4];
            Wlt[k4 * 4 + 0][nr] = vl.x;  Wrt[k4 * 4 + 0][nr] = vr.x;
            Wlt[k4 * 4 + 1][nr] = vl.y;  Wrt[k4 * 4 + 1][nr] = vr.y;
            Wlt[k4 * 4 + 2][nr] = vl.z;  Wrt[k4 * 4 + 2][nr] = vr.z;
            Wlt[k4 * 4 + 3][nr] = vl.w;  Wrt[k4 * 4 + 3][nr] = vr.w;
        }
        __syncthreads();

        #pragma unroll 4
        for (int k = 0; k < 32; k++) {
            ull wl2 = *(const ull*)&Wlt[k][2 * tx];
            ull wr2 = *(const ull*)&Wrt[k][2 * tx];
            const ull* arow = &As2[ty * 8 * 32 + k];
            #pragma unroll
            for (int i = 0; i < 8; i++) {
                ull a2 = arow[i * 32];           // LDS.64 broadcast
                FMA2(accl[i], a2, wl2);
                FMA2(accr[i], a2, wr2);
            }
        }
        __syncthreads();
    }

    // epilogue: packed bias add, 8-byte paired stores
    const int c0 = ncol0 + 2 * tx;
    ull bv2;
    {
        float2 b2 = *(const float2*)&bias[c0];
        bv2 = pack2(b2.x, b2.y);
    }
    #pragma unroll
    for (int i = 0; i < 8; i++) {
        int r = row0 + ty * 8 + i;
        if (r < n) {
            ull zr = accr[i];
            ADD2(zr, zr, bv2);
            *(ull*)&g_t[(size_t)r * DD + c0] = accl[i];
            *(ull*)&g_z[(size_t)r * DD + c0] = zr;
        }
    }
}

// ---------------- aggregate + finalize: dst = [relu](mean_agg(t) + z) -----
template <bool RELU, bool TO_OUT>
__global__ void aggregate_kernel(float* __restrict__ out, int n)
{
    int node = (blockIdx.x * blockDim.x + threadIdx.x) >> 5;
    int lane = threadIdx.x & 31;
    if (node >= n) return;

    int beg = g_rowptr[node];
    int end = g_rowptr[node + 1];
    const float4* t4 = (const float4*)g_t;

    float4 acc = make_float4(0.f, 0.f, 0.f, 0.f);
    int j = beg;
    for (; j + 4 <= end; j += 4) {
        int s0 = g_col[j], s1 = g_col[j + 1], s2 = g_col[j + 2], s3 = g_col[j + 3];
        float4 v0 = t4[(size_t)s0 * 32 + lane];
        float4 v1 = t4[(size_t)s1 * 32 + lane];
        float4 v2 = t4[(size_t)s2 * 32 + lane];
        float4 v3 = t4[(size_t)s3 * 32 + lane];
        acc.x += (v0.x + v1.x) + (v2.x + v3.x);
        acc.y += (v0.y + v1.y) + (v2.y + v3.y);
        acc.z += (v0.z + v1.z) + (v2.z + v3.z);
        acc.w += (v0.w + v1.w) + (v2.w + v3.w);
    }
    for (; j < end; j++) {
        int s = g_col[j];
        float4 v = t4[(size_t)s * 32 + lane];
        acc.x += v.x; acc.y += v.y; acc.z += v.z; acc.w += v.w;
    }

    float inv = g_inv[node];
    float4 z = ((const float4*)g_z)[(size_t)node * 32 + lane];
    float4 o;
    o.x = fmaf(acc.x, inv, z.x);
    o.y = fmaf(acc.y, inv, z.y);
    o.z = fmaf(acc.z, inv, z.z);
    o.w = fmaf(acc.w, inv, z.w);
    if (RELU) {
        o.x = fmaxf(o.x, 0.f); o.y = fmaxf(o.y, 0.f);
        o.z = fmaxf(o.z, 0.f); o.w = fmaxf(o.w, 0.f);
    }
    if (TO_OUT) ((float4*)out)[(size_t)node * 32 + lane] = o;
    else        ((float4*)g_h)[(size_t)node * 32 + lane] = o;
}

// ---------------- launch ----------------
extern "C" void kernel_launch(void* const* d_in, const int* in_sizes, int n_in,
                              void* d_out, int out_size)
{
    const float* x   = (const float*)d_in[0];
    const int*   ei  = (const int*)d_in[1];
    const float* Wl1 = (const float*)d_in[2];
    const float* Wr1 = (const float*)d_in[3];
    const float* b1  = (const float*)d_in[4];
    const float* Wl2 = (const float*)d_in[5];
    const float* Wr2 = (const float*)d_in[6];
    const float* b2  = (const float*)d_in[7];
    const float* Wl3 = (const float*)d_in[8];
    const float* Wr3 = (const float*)d_in[9];
    const float* b3  = (const float*)d_in[10];
    float* out = (float*)d_out;

    const int N = in_sizes[0] / DD;
    const int E = in_sizes[1] / 2;
    const int nb = (N + 255) / 256;

    // ---- stage input into symbol scratch ----
    const int n4 = N * 32;
    copy_in_kernel<<<(n4 + 255) / 256, 256>>>((const float4*)x, n4);

    // ---- edge dtype detection ----
    init_flag_kernel<<<1, 1>>>();
    detect_kernel<<<256, 256>>>(ei, E);

    // ---- CSR build ----
    zero_cnt_kernel<<<nb, 256>>>(N);
    hist_kernel<<<(E + 255) / 256, 256>>>(ei, E);
    scan1_kernel<<<nb, 256>>>(N);
    scan2_kernel<<<1, 1024>>>(nb);
    scan3_kernel<<<nb, 256>>>(N);
    fill_kernel<<<(E + 255) / 256, 256>>>(ei, E);

    dim3 gemm_grid((N + 63) / 64, 2);
    const int agg_grid = (N + 7) / 8;

    // ---- layer 1 ----
    gemm_dual_kernel<<<gemm_grid, 256>>>(Wl1, Wr1, b1, N);
    aggregate_kernel<true , false><<<agg_grid, 256>>>(out, N);
    // ---- layer 2 ----
    gemm_dual_kernel<<<gemm_grid, 256>>>(Wl2, Wr2, b2, N);
    aggregate_kernel<true , false><<<agg_grid, 256>>>(out, N);
    // ---- layer 3 ----
    gemm_dual_kernel<<<gemm_grid, 256>>>(Wl3, Wr3, b3, N);
    aggregate_kernel<false, true ><<<agg_grid, 256>>>(out, N);
}

// round 11
// speedup vs baseline: 1.1250x; 1.1250x over previous
#include <cuda_runtime.h>
#include <cuda_bf16.h>
#include <cstdint>

#define NMAX 100000
#define EMAX 1600000
#define DD   128
#define NTMAX 784   // max 128-row tiles

// ---------------- device scratch (symbol-only access, no allocations) -----
__device__ __align__(16) float g_t[(size_t)NMAX * DD];   // h @ W_l^T
__device__ __align__(16) float g_z[(size_t)NMAX * DD];   // h @ W_r^T + b
__device__ __align__(16) float g_h[(size_t)NMAX * DD];   // layer activations
__device__ __align__(16) unsigned char g_ahi[(size_t)NTMAX * 32768]; // bf16 [row][128]
__device__ __align__(16) unsigned char g_alo[(size_t)NTMAX * 32768];
__device__ __align__(16) unsigned char g_wbhi[6 * 32768];            // bf16 [n][128]
__device__ __align__(16) unsigned char g_wblo[6 * 32768];
__device__ int   g_rowptr[NMAX + 1];
__device__ int   g_cursor[NMAX];
__device__ int   g_col[EMAX];
__device__ float g_inv[NMAX];
__device__ int   g_cnt[NMAX];
__device__ int   g_bsum[1024];
__device__ int   g_boff[1024];
__device__ int   g_wide;

// bf16 mma.sync (HMMA — valid on base sm_103 target)
#define MMA(d, a, b) \
    asm volatile("mma.sync.aligned.m16n8k16.row.col.f32.bf16.bf16.f32 " \
        "{%0,%1,%2,%3}, {%4,%5,%6,%7}, {%8,%9}, {%0,%1,%2,%3};" \
        : "+f"((d)[0]), "+f"((d)[1]), "+f"((d)[2]), "+f"((d)[3]) \
        : "r"((a)[0]), "r"((a)[1]), "r"((a)[2]), "r"((a)[3]), \
          "r"((b)[0]), "r"((b)[1]))

// ---------------- edge dtype detection ------------------------------------
__global__ void detect_kernel(const int* __restrict__ ei, int E) {
    __shared__ int s_or;
    if (threadIdx.x == 0) s_or = 0;
    __syncthreads();
    int acc = 0;
    for (int i = blockIdx.x * blockDim.x + threadIdx.x; i < E; i += gridDim.x * blockDim.x)
        acc |= ei[2 * i + 1];
    if (acc) atomicOr(&s_or, 1);
    __syncthreads();
    if (threadIdx.x == 0 && s_or) g_wide = 0;
}
__global__ void init_flag_kernel() { g_wide = 1; }

// ---------------- CSR build ----------------
__global__ void zero_cnt_kernel(int n) {
    int i = blockIdx.x * blockDim.x + threadIdx.x;
    if (i < n) g_cnt[i] = 0;
}
__global__ void hist_kernel(const int* __restrict__ ei, int E) {
    int e = blockIdx.x * blockDim.x + threadIdx.x;
    if (e < E) {
        int dst = g_wide ? ei[2 * ((size_t)E + e)] : ei[(size_t)E + e];
        atomicAdd(&g_cnt[dst], 1);
    }
}
__global__ void scan1_kernel(int n) {
    __shared__ int sh[256];
    int i = blockIdx.x * 256 + threadIdx.x;
    sh[threadIdx.x] = (i < n) ? g_cnt[i] : 0;
    __syncthreads();
    for (int off = 128; off > 0; off >>= 1) {
        if (threadIdx.x < (unsigned)off) sh[threadIdx.x] += sh[threadIdx.x + off];
        __syncthreads();
    }
    if (threadIdx.x == 0) g_bsum[blockIdx.x] = sh[0];
}
__global__ void scan2_kernel(int nb) {
    __shared__ int sh[1024];
    int t = threadIdx.x;
    int v = (t < nb) ? g_bsum[t] : 0;
    sh[t] = v;
    __syncthreads();
    for (int off = 1; off < 1024; off <<= 1) {
        int u = (t >= off) ? sh[t - off] : 0;
        __syncthreads();
        sh[t] += u;
        __syncthreads();
    }
    if (t < nb) g_boff[t] = sh[t] - v;
}
__global__ void scan3_kernel(int n) {
    __shared__ int sh[256];
    int i = blockIdx.x * 256 + threadIdx.x;
    int v = (i < n) ? g_cnt[i] : 0;
    sh[threadIdx.x] = v;
    __syncthreads();
    for (int off = 1; off < 256; off <<= 1) {
        int u = ((int)threadIdx.x >= off) ? sh[threadIdx.x - off] : 0;
        __syncthreads();
        sh[threadIdx.x] += u;
        __syncthreads();
    }
    if (i < n) {
        int incl = sh[threadIdx.x] + g_boff[blockIdx.x];
        g_rowptr[i + 1] = incl;
        g_cursor[i]     = incl - v;
        g_inv[i]        = 1.0f / fmaxf((float)v, 1.0f);
    }
    if (blockIdx.x == 0 && threadIdx.x == 0) g_rowptr[0] = 0;
}
__global__ void fill_kernel(const int* __restrict__ ei, int E) {
    int e = blockIdx.x * blockDim.x + threadIdx.x;
    if (e < E) {
        int wide = g_wide;
        int src = wide ? ei[2 * (size_t)e]        : ei[e];
        int dst = wide ? ei[2 * ((size_t)E + e)]  : ei[(size_t)E + e];
        int pos = atomicAdd(&g_cursor[dst], 1);
        g_col[pos] = src;
    }
}

// ---------------- fp32 -> bf16 hi/lo split (row-major images) -------------
__device__ __forceinline__ void split8(const float* v, uint32_t* hi, uint32_t* lo) {
    #pragma unroll
    for (int j = 0; j < 4; j++) {
        __nv_bfloat16 h0 = __float2bfloat16(v[2 * j]);
        __nv_bfloat16 h1 = __float2bfloat16(v[2 * j + 1]);
        float r0 = v[2 * j]     - __bfloat162float(h0);
        float r1 = v[2 * j + 1] - __bfloat162float(h1);
        __nv_bfloat16 l0 = __float2bfloat16(r0);
        __nv_bfloat16 l1 = __float2bfloat16(r1);
        hi[j] = (uint32_t)__bfloat16_as_ushort(h0) | ((uint32_t)__bfloat16_as_ushort(h1) << 16);
        lo[j] = (uint32_t)__bfloat16_as_ushort(l0) | ((uint32_t)__bfloat16_as_ushort(l1) << 16);
    }
}

template <bool FROM_X>
__global__ void convert_a_kernel(const float* __restrict__ x, int n, int ntiles) {
    int id = blockIdx.x * 256 + threadIdx.x;
    if (id >= ntiles * 2048) return;
    int g = id & 15;             // k-group of 8
    int row = id >> 4;           // 0 .. ntiles*128-1
    const float* src = FROM_X ? x : (const float*)g_h;
    float v[8];
    if (row < n) {
        float4 p = ((const float4*)src)[(size_t)row * 32 + 2 * g];
        float4 q = ((const float4*)src)[(size_t)row * 32 + 2 * g + 1];
        v[0] = p.x; v[1] = p.y; v[2] = p.z; v[3] = p.w;
        v[4] = q.x; v[5] = q.y; v[6] = q.z; v[7] = q.w;
    } else {
        #pragma unroll
        for (int j = 0; j < 8; j++) v[j] = 0.f;
    }
    uint32_t hi[4], lo[4];
    split8(v, hi, lo);
    size_t dst = (size_t)row * 256 + g * 16;
    *(uint4*)(g_ahi + dst) = make_uint4(hi[0], hi[1], hi[2], hi[3]);
    *(uint4*)(g_alo + dst) = make_uint4(lo[0], lo[1], lo[2], lo[3]);
}

__global__ void convert_w_kernel(const float* __restrict__ W0, const float* __restrict__ W1,
                                 const float* __restrict__ W2, const float* __restrict__ W3,
                                 const float* __restrict__ W4, const float* __restrict__ W5) {
    int m = blockIdx.x;
    const float* W = (m == 0) ? W0 : (m == 1) ? W1 : (m == 2) ? W2
                   : (m == 3) ? W3 : (m == 4) ? W4 : W5;
    int id = blockIdx.y * 256 + threadIdx.x;   // 0..2047
    int g = id & 15;
    int r = id >> 4;                            // 0..127
    float4 p = ((const float4*)W)[r * 32 + 2 * g];
    float4 q = ((const float4*)W)[r * 32 + 2 * g + 1];
    float v[8] = {p.x, p.y, p.z, p.w, q.x, q.y, q.z, q.w};
    uint32_t hi[4], lo[4];
    split8(v, hi, lo);
    size_t dst = (size_t)m * 32768 + (size_t)r * 256 + g * 16;
    *(uint4*)(g_wbhi + dst) = make_uint4(hi[0], hi[1], hi[2], hi[3]);
    *(uint4*)(g_wblo + dst) = make_uint4(lo[0], lo[1], lo[2], lo[3]);
}

// ---------------- split-bf16 mma.sync dual GEMM ---------------------------
// grid.y=0: g_t = A@Wl^T ; grid.y=1: g_z = A@Wr^T + b.
// CTA 256thr -> 128x128 tile; warps 2(M)x4(N); warp tile 64x32.
__global__ __launch_bounds__(256, 1)
void gemm_mma_kernel(const float* __restrict__ bias, int layer, int n)
{
    const int tid  = threadIdx.x;
    const int wid  = tid >> 5, lane = tid & 31;
    const int gid  = lane >> 2, tig = lane & 3;
    const int warpM = wid >> 2, warpN = wid & 3;
    const int row0 = blockIdx.x * 128 + warpM * 64;
    const int half = blockIdx.y;
    const int widx = 2 * layer + half;

    const uint32_t* A_hi = (const uint32_t*)g_ahi;   // idx = row*64 + k/2
    const uint32_t* A_lo = (const uint32_t*)g_alo;
    const uint32_t* B_hi = (const uint32_t*)(g_wbhi + (size_t)widx * 32768);
    const uint32_t* B_lo = (const uint32_t*)(g_wblo + (size_t)widx * 32768);

    float acc[4][4][4];
    #pragma unroll
    for (int mi = 0; mi < 4; mi++)
        #pragma unroll
        for (int ni = 0; ni < 4; ni++)
            acc[mi][ni][0] = acc[mi][ni][1] = acc[mi][ni][2] = acc[mi][ni][3] = 0.f;

    const int rA = row0 + gid;
    const int nB = warpN * 32 + gid;

    #pragma unroll 2
    for (int kk2 = 0; kk2 < 64; kk2 += 8) {   // k/2 in steps of 8 (k16)
        uint32_t ah[4][4], al[4][4], bh[4][2], bl[4][2];
        #pragma unroll
        for (int mi = 0; mi < 4; mi++) {
            int base0 = (rA + mi * 16)     * 64 + kk2 + tig;
            int base1 = (rA + mi * 16 + 8) * 64 + kk2 + tig;
            ah[mi][0] = A_hi[base0];     ah[mi][1] = A_hi[base1];
            ah[mi][2] = A_hi[base0 + 4]; ah[mi][3] = A_hi[base1 + 4];
            al[mi][0] = A_lo[base0];     al[mi][1] = A_lo[base1];
            al[mi][2] = A_lo[base0 + 4]; al[mi][3] = A_lo[base1 + 4];
        }
        #pragma unroll
        for (int ni = 0; ni < 4; ni++) {
            int b0 = (nB + ni * 8) * 64 + kk2 + tig;
            bh[ni][0] = B_hi[b0]; bh[ni][1] = B_hi[b0 + 4];
            bl[ni][0] = B_lo[b0]; bl[ni][1] = B_lo[b0 + 4];
        }
        #pragma unroll
        for (int mi = 0; mi < 4; mi++)
            #pragma unroll
            for (int ni = 0; ni < 4; ni++) {
                MMA(acc[mi][ni], ah[mi], bh[ni]);
                MMA(acc[mi][ni], ah[mi], bl[ni]);
                MMA(acc[mi][ni], al[mi], bh[ni]);
            }
    }

    // epilogue
    float* gout = half ? g_z : g_t;
    #pragma unroll
    for (int ni = 0; ni < 4; ni++) {
        int col = warpN * 32 + ni * 8 + 2 * tig;
        float2 bv = make_float2(0.f, 0.f);
        if (half) bv = *(const float2*)&bias[col];
        #pragma unroll
        for (int mi = 0; mi < 4; mi++) {
            int r0 = row0 + mi * 16 + gid;
            if (r0 < n)
                *(float2*)&gout[(size_t)r0 * DD + col] =
                    make_float2(acc[mi][ni][0] + bv.x, acc[mi][ni][1] + bv.y);
            if (r0 + 8 < n)
                *(float2*)&gout[(size_t)(r0 + 8) * DD + col] =
                    make_float2(acc[mi][ni][2] + bv.x, acc[mi][ni][3] + bv.y);
        }
    }
}

// ---------------- aggregate + finalize: dst = [relu](mean_agg(t) + z) -----
template <bool RELU, bool TO_OUT>
__global__ void aggregate_kernel(float* __restrict__ out, int n)
{
    int node = (blockIdx.x * blockDim.x + threadIdx.x) >> 5;
    int lane = threadIdx.x & 31;
    if (node >= n) return;

    int beg = g_rowptr[node];
    int end = g_rowptr[node + 1];
    const float4* t4 = (const float4*)g_t;

    float4 acc = make_float4(0.f, 0.f, 0.f, 0.f);
    int j = beg;
    for (; j + 4 <= end; j += 4) {
        int s0 = g_col[j], s1 = g_col[j + 1], s2 = g_col[j + 2], s3 = g_col[j + 3];
        float4 v0 = t4[(size_t)s0 * 32 + lane];
        float4 v1 = t4[(size_t)s1 * 32 + lane];
        float4 v2 = t4[(size_t)s2 * 32 + lane];
        float4 v3 = t4[(size_t)s3 * 32 + lane];
        acc.x += (v0.x + v1.x) + (v2.x + v3.x);
        acc.y += (v0.y + v1.y) + (v2.y + v3.y);
        acc.z += (v0.z + v1.z) + (v2.z + v3.z);
        acc.w += (v0.w + v1.w) + (v2.w + v3.w);
    }
    for (; j < end; j++) {
        int s = g_col[j];
        float4 v = t4[(size_t)s * 32 + lane];
        acc.x += v.x; acc.y += v.y; acc.z += v.z; acc.w += v.w;
    }

    float inv = g_inv[node];
    float4 z = ((const float4*)g_z)[(size_t)node * 32 + lane];
    float4 o;
    o.x = fmaf(acc.x, inv, z.x);
    o.y = fmaf(acc.y, inv, z.y);
    o.z = fmaf(acc.z, inv, z.z);
    o.w = fmaf(acc.w, inv, z.w);
    if (RELU) {
        o.x = fmaxf(o.x, 0.f); o.y = fmaxf(o.y, 0.f);
        o.z = fmaxf(o.z, 0.f); o.w = fmaxf(o.w, 0.f);
    }
    if (TO_OUT) ((float4*)out)[(size_t)node * 32 + lane] = o;
    else        ((float4*)g_h)[(size_t)node * 32 + lane] = o;
}

// ---------------- launch ----------------
extern "C" void kernel_launch(void* const* d_in, const int* in_sizes, int n_in,
                              void* d_out, int out_size)
{
    const float* x   = (const float*)d_in[0];
    const int*   ei  = (const int*)d_in[1];
    const float* Wl1 = (const float*)d_in[2];
    const float* Wr1 = (const float*)d_in[3];
    const float* b1  = (const float*)d_in[4];
    const float* Wl2 = (const float*)d_in[5];
    const float* Wr2 = (const float*)d_in[6];
    const float* b2  = (const float*)d_in[7];
    const float* Wl3 = (const float*)d_in[8];
    const float* Wr3 = (const float*)d_in[9];
    const float* b3  = (const float*)d_in[10];
    float* out = (float*)d_out;

    const int N = in_sizes[0] / DD;
    const int E = in_sizes[1] / 2;
    const int nb = (N + 255) / 256;
    const int ntiles = (N + 127) / 128;

    // ---- edge dtype detection + CSR ----
    init_flag_kernel<<<1, 1>>>();
    detect_kernel<<<256, 256>>>(ei, E);
    zero_cnt_kernel<<<nb, 256>>>(N);
    hist_kernel<<<(E + 255) / 256, 256>>>(ei, E);
    scan1_kernel<<<nb, 256>>>(N);
    scan2_kernel<<<1, 1024>>>(nb);
    scan3_kernel<<<nb, 256>>>(N);
    fill_kernel<<<(E + 255) / 256, 256>>>(ei, E);

    // ---- weights -> split-bf16 images ----
    convert_w_kernel<<<dim3(6, 8), 256>>>(Wl1, Wr1, Wl2, Wr2, Wl3, Wr3);

    const int cgrid = ntiles * 8;
    dim3 ggrid(ntiles, 2);
    const int agg_grid = (N + 7) / 8;

    // ---- layer 1 ----
    convert_a_kernel<true ><<<cgrid, 256>>>(x, N, ntiles);
    gemm_mma_kernel<<<ggrid, 256>>>(b1, 0, N);
    aggregate_kernel<true , false><<<agg_grid, 256>>>(out, N);
    // ---- layer 2 ----
    convert_a_kernel<false><<<cgrid, 256>>>(x, N, ntiles);
    gemm_mma_kernel<<<ggrid, 256>>>(b2, 1, N);
    aggregate_kernel<true , false><<<agg_grid, 256>>>(out, N);
    // ---- layer 3 ----
    convert_a_kernel<false><<<cgrid, 256>>>(x, N, ntiles);
    gemm_mma_kernel<<<ggrid, 256>>>(b3, 2, N);
    aggregate_kernel<false, true ><<<agg_grid, 256>>>(out, N);
}

// round 14
// speedup vs baseline: 1.8370x; 1.6329x over previous
#include <cuda_runtime.h>
#include <cuda_bf16.h>
#include <cstdint>

#define NMAX 100000
#define EMAX 1600000
#define DD   128
#define NTMAX 784   // max 128-row tiles

// ---------------- device scratch (symbol-only access, no allocations) -----
__device__ __align__(16) float g_t[(size_t)NMAX * DD];   // h @ W_l^T
__device__ __align__(16) float g_z[(size_t)NMAX * DD];   // h @ W_r^T + b
__device__ __align__(16) float g_h[(size_t)NMAX * DD];   // layer activations
// fragment-packed bf16 images (A: 512B blob per 16x16 block; W: 256B per 8x16)
__device__ __align__(16) unsigned char g_ahi[(size_t)NTMAX * 32768];
__device__ __align__(16) unsigned char g_alo[(size_t)NTMAX * 32768];
__device__ __align__(16) unsigned char g_wbhi[6 * 32768];
__device__ __align__(16) unsigned char g_wblo[6 * 32768];
__device__ int   g_rowptr[NMAX + 1];
__device__ int   g_cursor[NMAX];
__device__ int   g_col[EMAX];
__device__ float g_inv[NMAX];
__device__ int   g_cnt[NMAX];
__device__ int   g_bsum[1024];
__device__ int   g_boff[1024];
__device__ int   g_wide;

// bf16 mma.sync (HMMA — valid on base sm_103 target)
#define MMA(d, a, b) \
    asm volatile("mma.sync.aligned.m16n8k16.row.col.f32.bf16.bf16.f32 " \
        "{%0,%1,%2,%3}, {%4,%5,%6,%7}, {%8,%9}, {%0,%1,%2,%3};" \
        : "+f"((d)[0]), "+f"((d)[1]), "+f"((d)[2]), "+f"((d)[3]) \
        : "r"((a)[0]), "r"((a)[1]), "r"((a)[2]), "r"((a)[3]), \
          "r"((b)[0]), "r"((b)[1]))

__device__ __forceinline__ uint32_t pack_bf16x2(float a, float b) {
    __nv_bfloat16 ha = __float2bfloat16(a);
    __nv_bfloat16 hb = __float2bfloat16(b);
    return (uint32_t)__bfloat16_as_ushort(ha) | ((uint32_t)__bfloat16_as_ushort(hb) << 16);
}
__device__ __forceinline__ uint32_t pack_lo(float a, float b, uint32_t hiw) {
    float ra = a - __bfloat162float(__ushort_as_bfloat16((unsigned short)(hiw & 0xFFFF)));
    float rb = b - __bfloat162float(__ushort_as_bfloat16((unsigned short)(hiw >> 16)));
    return pack_bf16x2(ra, rb);
}

// ---------------- edge dtype detection ------------------------------------
__global__ void detect_kernel(const int* __restrict__ ei, int E) {
    __shared__ int s_or;
    if (threadIdx.x == 0) s_or = 0;
    __syncthreads();
    int acc = 0;
    for (int i = blockIdx.x * blockDim.x + threadIdx.x; i < E; i += gridDim.x * blockDim.x)
        acc |= ei[2 * i + 1];
    if (acc) atomicOr(&s_or, 1);
    __syncthreads();
    if (threadIdx.x == 0 && s_or) g_wide = 0;
}
__global__ void init_flag_kernel() { g_wide = 1; }

// ---------------- CSR build ----------------
__global__ void zero_cnt_kernel(int n) {
    int i = blockIdx.x * blockDim.x + threadIdx.x;
    if (i < n) g_cnt[i] = 0;
}
__global__ void hist_kernel(const int* __restrict__ ei, int E) {
    int e = blockIdx.x * blockDim.x + threadIdx.x;
    if (e < E) {
        int dst = g_wide ? ei[2 * ((size_t)E + e)] : ei[(size_t)E + e];
        atomicAdd(&g_cnt[dst], 1);
    }
}
__global__ void scan1_kernel(int n) {
    __shared__ int sh[256];
    int i = blockIdx.x * 256 + threadIdx.x;
    sh[threadIdx.x] = (i < n) ? g_cnt[i] : 0;
    __syncthreads();
    for (int off = 128; off > 0; off >>= 1) {
        if (threadIdx.x < (unsigned)off) sh[threadIdx.x] += sh[threadIdx.x + off];
        __syncthreads();
    }
    if (threadIdx.x == 0) g_bsum[blockIdx.x] = sh[0];
}
__global__ void scan2_kernel(int nb) {
    __shared__ int sh[1024];
    int t = threadIdx.x;
    int v = (t < nb) ? g_bsum[t] : 0;
    sh[t] = v;
    __syncthreads();
    for (int off = 1; off < 1024; off <<= 1) {
        int u = (t >= off) ? sh[t - off] : 0;
        __syncthreads();
        sh[t] += u;
        __syncthreads();
    }
    if (t < nb) g_boff[t] = sh[t] - v;
}
__global__ void scan3_kernel(int n) {
    __shared__ int sh[256];
    int i = blockIdx.x * 256 + threadIdx.x;
    int v = (i < n) ? g_cnt[i] : 0;
    sh[threadIdx.x] = v;
    __syncthreads();
    for (int off = 1; off < 256; off <<= 1) {
        int u = ((int)threadIdx.x >= off) ? sh[threadIdx.x - off] : 0;
        __syncthreads();
        sh[threadIdx.x] += u;
        __syncthreads();
    }
    if (i < n) {
        int incl = sh[threadIdx.x] + g_boff[blockIdx.x];
        g_rowptr[i + 1] = incl;
        g_cursor[i]     = incl - v;
        g_inv[i]        = 1.0f / fmaxf((float)v, 1.0f);
    }
    if (blockIdx.x == 0 && threadIdx.x == 0) g_rowptr[0] = 0;
}
__global__ void fill_kernel(const int* __restrict__ ei, int E) {
    int e = blockIdx.x * blockDim.x + threadIdx.x;
    if (e < E) {
        int wide = g_wide;
        int src = wide ? ei[2 * (size_t)e]        : ei[e];
        int dst = wide ? ei[2 * ((size_t)E + e)]  : ei[(size_t)E + e];
        int pos = atomicAdd(&g_cursor[dst], 1);
        g_col[pos] = src;
    }
}

// ---------------- converters: fp32 -> fragment-packed split-bf16 ----------
// A blob (per m-block mb of 16 rows x k-block kb of 16 cols): 128 words.
// word index = lane*4 + w; lane=(g,t): w0=(row g,  kw t), w1=(row g+8, kw t),
// w2=(row g, kw t+4), w3=(row g+8, kw t+4). Blob id = mb*8+kb.
template <bool FROM_X>
__global__ void convert_a_kernel(const float* __restrict__ x, int n, int ntiles) {
    int id = blockIdx.x * 256 + threadIdx.x;      // one thread per (blob, lane)
    if (id >= ntiles * 2048) return;
    int lane = id & 31;
    int blob = id >> 5;
    int kb = blob & 7;
    int mb = blob >> 3;
    int g = lane >> 2, t = lane & 3;
    int r0 = mb * 16 + g;
    int c0 = kb * 16 + 2 * t;                      // k for word pair (t)
    const float* src = FROM_X ? x : (const float*)g_h;

    float v[8];                                    // pairs: (r0,c0) (r0+8,c0) (r0,c0+8) (r0+8,c0+8)
    #pragma unroll
    for (int p = 0; p < 4; p++) {
        int r = r0 + (p & 1) * 8;
        int c = c0 + (p >> 1) * 8;
        float2 f = (r < n) ? *(const float2*)&src[(size_t)r * DD + c]
                           : make_float2(0.f, 0.f);
        v[2 * p] = f.x; v[2 * p + 1] = f.y;
    }
    uint32_t hi[4], lo[4];
    #pragma unroll
    for (int p = 0; p < 4; p++) {
        hi[p] = pack_bf16x2(v[2 * p], v[2 * p + 1]);
        lo[p] = pack_lo(v[2 * p], v[2 * p + 1], hi[p]);
    }
    size_t dst = (size_t)blob * 512 + lane * 16;
    *(uint4*)(g_ahi + dst) = make_uint4(hi[0], hi[1], hi[2], hi[3]);
    *(uint4*)(g_alo + dst) = make_uint4(lo[0], lo[1], lo[2], lo[3]);
}

// W blob (per n-block nb of 8 cols x k-block kb): 64 words.
// word = lane*2 + w; lane=(g,t): w0=(n g, kw t), w1=(n g, kw t+4). Blob id = nb*8+kb.
__global__ void convert_w_kernel(const float* __restrict__ W0, const float* __restrict__ W1,
                                 const float* __restrict__ W2, const float* __restrict__ W3,
                                 const float* __restrict__ W4, const float* __restrict__ W5) {
    int m = blockIdx.x;
    const float* W = (m == 0) ? W0 : (m == 1) ? W1 : (m == 2) ? W2
                   : (m == 3) ? W3 : (m == 4) ? W4 : W5;
    int id = blockIdx.y * 256 + threadIdx.x;       // 0..4095
    int lane = id & 31;
    int blob = id >> 5;                            // 0..127
    int kb = blob & 7;
    int nb = blob >> 3;
    int g = lane >> 2, t = lane & 3;
    int nrow = nb * 8 + g;
    int c0 = kb * 16 + 2 * t;

    float2 f0 = *(const float2*)&W[nrow * DD + c0];
    float2 f1 = *(const float2*)&W[nrow * DD + c0 + 8];
    uint32_t h0 = pack_bf16x2(f0.x, f0.y);
    uint32_t h1 = pack_bf16x2(f1.x, f1.y);
    uint32_t l0 = pack_lo(f0.x, f0.y, h0);
    uint32_t l1 = pack_lo(f1.x, f1.y, h1);
    size_t dst = (size_t)m * 32768 + (size_t)blob * 256 + lane * 8;
    *(uint2*)(g_wbhi + dst) = make_uint2(h0, h1);
    *(uint2*)(g_wblo + dst) = make_uint2(l0, l1);
}

// ---------------- split-bf16 mma.sync dual GEMM (packed operands) ---------
// grid.y=0: g_t = A@Wl^T ; grid.y=1: g_z = A@Wr^T + b.
// CTA 256thr -> 128x128 tile; warps 2(M)x4(N); warp tile 64x32.
__global__ __launch_bounds__(256, 1)
void gemm_mma_kernel(const float* __restrict__ bias, int layer, int n)
{
    const int tid  = threadIdx.x;
    const int wid  = tid >> 5, lane = tid & 31;
    const int gid  = lane >> 2, tig = lane & 3;
    const int warpM = wid >> 2, warpN = wid & 3;
    const int row0 = blockIdx.x * 128 + warpM * 64;
    const int mb0  = row0 >> 4;                    // first m-block (of 4)
    const int nb0  = warpN * 4;                    // first n-block (of 4)
    const int half = blockIdx.y;
    const int widx = 2 * layer + half;

    const uint4* Ahi = (const uint4*)g_ahi;        // blob*32 + lane  (uint4 units)
    const uint4* Alo = (const uint4*)g_alo;
    const uint2* Bhi = (const uint2*)(g_wbhi + (size_t)widx * 32768);
    const uint2* Blo = (const uint2*)(g_wblo + (size_t)widx * 32768);

    float acc[4][4][4];
    #pragma unroll
    for (int mi = 0; mi < 4; mi++)
        #pragma unroll
        for (int ni = 0; ni < 4; ni++)
            acc[mi][ni][0] = acc[mi][ni][1] = acc[mi][ni][2] = acc[mi][ni][3] = 0.f;

    #pragma unroll 2
    for (int kb = 0; kb < 8; kb++) {
        uint4 ah[4], al[4];
        uint2 bh[4], bl[4];
        #pragma unroll
        for (int mi = 0; mi < 4; mi++) {
            int bidx = ((mb0 + mi) * 8 + kb) * 32 + lane;
            ah[mi] = Ahi[bidx];
            al[mi] = Alo[bidx];
        }
        #pragma unroll
        for (int ni = 0; ni < 4; ni++) {
            int bidx = ((nb0 + ni) * 8 + kb) * 32 + lane;
            bh[ni] = Bhi[bidx];
            bl[ni] = Blo[bidx];
        }
        #pragma unroll
        for (int mi = 0; mi < 4; mi++)
            #pragma unroll
            for (int ni = 0; ni < 4; ni++) {
                MMA(acc[mi][ni], (&ah[mi].x), (&bh[ni].x));
                MMA(acc[mi][ni], (&ah[mi].x), (&bl[ni].x));
                MMA(acc[mi][ni], (&al[mi].x), (&bh[ni].x));
            }
    }

    // epilogue
    float* gout = half ? g_z : g_t;
    #pragma unroll
    for (int ni = 0; ni < 4; ni++) {
        int col = warpN * 32 + ni * 8 + 2 * tig;
        float2 bv = make_float2(0.f, 0.f);
        if (half) bv = *(const float2*)&bias[col];
        #pragma unroll
        for (int mi = 0; mi < 4; mi++) {
            int r0 = row0 + mi * 16 + gid;
            if (r0 < n)
                *(float2*)&gout[(size_t)r0 * DD + col] =
                    make_float2(acc[mi][ni][0] + bv.x, acc[mi][ni][1] + bv.y);
            if (r0 + 8 < n)
                *(float2*)&gout[(size_t)(r0 + 8) * DD + col] =
                    make_float2(acc[mi][ni][2] + bv.x, acc[mi][ni][3] + bv.y);
        }
    }
}

// ---------------- aggregate + finalize: dst = [relu](mean_agg(t) + z) -----
template <bool RELU, bool TO_OUT>
__global__ void aggregate_kernel(float* __restrict__ out, int n)
{
    int node = (blockIdx.x * blockDim.x + threadIdx.x) >> 5;
    int lane = threadIdx.x & 31;
    if (node >= n) return;

    int beg = g_rowptr[node];
    int end = g_rowptr[node + 1];
    const float4* t4 = (const float4*)g_t;

    float4 acc = make_float4(0.f, 0.f, 0.f, 0.f);
    int j = beg;
    for (; j + 4 <= end; j += 4) {
        int s0 = g_col[j], s1 = g_col[j + 1], s2 = g_col[j + 2], s3 = g_col[j + 3];
        float4 v0 = t4[(size_t)s0 * 32 + lane];
        float4 v1 = t4[(size_t)s1 * 32 + lane];
        float4 v2 = t4[(size_t)s2 * 32 + lane];
        float4 v3 = t4[(size_t)s3 * 32 + lane];
        acc.x += (v0.x + v1.x) + (v2.x + v3.x);
        acc.y += (v0.y + v1.y) + (v2.y + v3.y);
        acc.z += (v0.z + v1.z) + (v2.z + v3.z);
        acc.w += (v0.w + v1.w) + (v2.w + v3.w);
    }
    for (; j < end; j++) {
        int s = g_col[j];
        float4 v = t4[(size_t)s * 32 + lane];
        acc.x += v.x; acc.y += v.y; acc.z += v.z; acc.w += v.w;
    }

    float inv = g_inv[node];
    float4 z = ((const float4*)g_z)[(size_t)node * 32 + lane];
    float4 o;
    o.x = fmaf(acc.x, inv, z.x);
    o.y = fmaf(acc.y, inv, z.y);
    o.z = fmaf(acc.z, inv, z.z);
    o.w = fmaf(acc.w, inv, z.w);
    if (RELU) {
        o.x = fmaxf(o.x, 0.f); o.y = fmaxf(o.y, 0.f);
        o.z = fmaxf(o.z, 0.f); o.w = fmaxf(o.w, 0.f);
    }
    if (TO_OUT) ((float4*)out)[(size_t)node * 32 + lane] = o;
    else        ((float4*)g_h)[(size_t)node * 32 + lane] = o;
}

// ---------------- launch ----------------
extern "C" void kernel_launch(void* const* d_in, const int* in_sizes, int n_in,
                              void* d_out, int out_size)
{
    const float* x   = (const float*)d_in[0];
    const int*   ei  = (const int*)d_in[1];
    const float* Wl1 = (const float*)d_in[2];
    const float* Wr1 = (const float*)d_in[3];
    const float* b1  = (const float*)d_in[4];
    const float* Wl2 = (const float*)d_in[5];
    const float* Wr2 = (const float*)d_in[6];
    const float* b2  = (const float*)d_in[7];
    const float* Wl3 = (const float*)d_in[8];
    const float* Wr3 = (const float*)d_in[9];
    const float* b3  = (const float*)d_in[10];
    float* out = (float*)d_out;

    const int N = in_sizes[0] / DD;
    const int E = in_sizes[1] / 2;
    const int nb = (N + 255) / 256;
    const int ntiles = (N + 127) / 128;

    // ---- edge dtype detection + CSR ----
    init_flag_kernel<<<1, 1>>>();
    detect_kernel<<<256, 256>>>(ei, E);
    zero_cnt_kernel<<<nb, 256>>>(N);
    hist_kernel<<<(E + 255) / 256, 256>>>(ei, E);
    scan1_kernel<<<nb, 256>>>(N);
    scan2_kernel<<<1, 1024>>>(nb);
    scan3_kernel<<<nb, 256>>>(N);
    fill_kernel<<<(E + 255) / 256, 256>>>(ei, E);

    // ---- weights -> fragment-packed split-bf16 ----
    convert_w_kernel<<<dim3(6, 16), 256>>>(Wl1, Wr1, Wl2, Wr2, Wl3, Wr3);

    const int cgrid = ntiles * 8;
    dim3 ggrid(ntiles, 2);
    const int agg_grid = (N + 7) / 8;

    // ---- layer 1 ----
    convert_a_kernel<true ><<<cgrid, 256>>>(x, N, ntiles);
    gemm_mma_kernel<<<ggrid, 256>>>(b1, 0, N);
    aggregate_kernel<true , false><<<agg_grid, 256>>>(out, N);
    // ---- layer 2 ----
    convert_a_kernel<false><<<cgrid, 256>>>(x, N, ntiles);
    gemm_mma_kernel<<<ggrid, 256>>>(b2, 1, N);
    aggregate_kernel<true , false><<<agg_grid, 256>>>(out, N);
    // ---- layer 3 ----
    convert_a_kernel<false><<<cgrid, 256>>>(x, N, ntiles);
    gemm_mma_kernel<<<ggrid, 256>>>(b3, 2, N);
    aggregate_kernel<false, true ><<<agg_grid, 256>>>(out, N);
}

// round 16
// speedup vs baseline: 2.0354x; 1.1080x over previous
#include <cuda_runtime.h>
#include <cuda_bf16.h>
#include <cuda_fp16.h>
#include <cstdint>

#define NMAX 100000
#define EMAX 1600000
#define DD   128
#define NTMAX 784   // max 128-row tiles

// ---------------- device scratch (symbol-only access, no allocations) -----
__device__ __align__(16) float g_t[(size_t)NMAX * DD / 2]; // t as half2 (aliased)
__device__ __align__(16) float g_z[(size_t)NMAX * DD];     // h @ W_r^T + b
// fragment-packed bf16 images (A: 512B blob per 16x16 block; W: 256B per 8x16)
__device__ __align__(16) unsigned char g_ahi[(size_t)NTMAX * 32768];
__device__ __align__(16) unsigned char g_alo[(size_t)NTMAX * 32768];
__device__ __align__(16) unsigned char g_wbhi[6 * 32768];
__device__ __align__(16) unsigned char g_wblo[6 * 32768];
__device__ int   g_rowptr[NMAX + 1];
__device__ int   g_cursor[NMAX];
__device__ int   g_col[EMAX];
__device__ float g_inv[NMAX];
__device__ int   g_cnt[NMAX];
__device__ int   g_bsum[1024];
__device__ int   g_boff[1024];
__device__ int   g_wide;

// bf16 mma.sync (HMMA — valid on base sm_103 target)
#define MMA(d, a, b) \
    asm volatile("mma.sync.aligned.m16n8k16.row.col.f32.bf16.bf16.f32 " \
        "{%0,%1,%2,%3}, {%4,%5,%6,%7}, {%8,%9}, {%0,%1,%2,%3};" \
        : "+f"((d)[0]), "+f"((d)[1]), "+f"((d)[2]), "+f"((d)[3]) \
        : "r"((a)[0]), "r"((a)[1]), "r"((a)[2]), "r"((a)[3]), \
          "r"((b)[0]), "r"((b)[1]))

__device__ __forceinline__ uint32_t pack_bf16x2(float a, float b) {
    __nv_bfloat16 ha = __float2bfloat16(a);
    __nv_bfloat16 hb = __float2bfloat16(b);
    return (uint32_t)__bfloat16_as_ushort(ha) | ((uint32_t)__bfloat16_as_ushort(hb) << 16);
}
__device__ __forceinline__ uint32_t pack_lo(float a, float b, uint32_t hiw) {
    float ra = a - __bfloat162float(__ushort_as_bfloat16((unsigned short)(hiw & 0xFFFF)));
    float rb = b - __bfloat162float(__ushort_as_bfloat16((unsigned short)(hiw >> 16)));
    return pack_bf16x2(ra, rb);
}

// ---------------- edge dtype detection ------------------------------------
__global__ void detect_kernel(const int* __restrict__ ei, int E) {
    __shared__ int s_or;
    if (threadIdx.x == 0) s_or = 0;
    __syncthreads();
    int acc = 0;
    for (int i = blockIdx.x * blockDim.x + threadIdx.x; i < E; i += gridDim.x * blockDim.x)
        acc |= ei[2 * i + 1];
    if (acc) atomicOr(&s_or, 1);
    __syncthreads();
    if (threadIdx.x == 0 && s_or) g_wide = 0;
}
__global__ void init_flag_kernel() { g_wide = 1; }

// ---------------- CSR build ----------------
__global__ void zero_cnt_kernel(int n) {
    int i = blockIdx.x * blockDim.x + threadIdx.x;
    if (i < n) g_cnt[i] = 0;
}
__global__ void hist_kernel(const int* __restrict__ ei, int E) {
    int e = blockIdx.x * blockDim.x + threadIdx.x;
    if (e < E) {
        int dst = g_wide ? ei[2 * ((size_t)E + e)] : ei[(size_t)E + e];
        atomicAdd(&g_cnt[dst], 1);
    }
}
__global__ void scan1_kernel(int n) {
    __shared__ int sh[256];
    int i = blockIdx.x * 256 + threadIdx.x;
    sh[threadIdx.x] = (i < n) ? g_cnt[i] : 0;
    __syncthreads();
    for (int off = 128; off > 0; off >>= 1) {
        if (threadIdx.x < (unsigned)off) sh[threadIdx.x] += sh[threadIdx.x + off];
        __syncthreads();
    }
    if (threadIdx.x == 0) g_bsum[blockIdx.x] = sh[0];
}
__global__ void scan2_kernel(int nb) {
    __shared__ int sh[1024];
    int t = threadIdx.x;
    int v = (t < nb) ? g_bsum[t] : 0;
    sh[t] = v;
    __syncthreads();
    for (int off = 1; off < 1024; off <<= 1) {
        int u = (t >= off) ? sh[t - off] : 0;
        __syncthreads();
        sh[t] += u;
        __syncthreads();
    }
    if (t < nb) g_boff[t] = sh[t] - v;
}
__global__ void scan3_kernel(int n) {
    __shared__ int sh[256];
    int i = blockIdx.x * 256 + threadIdx.x;
    int v = (i < n) ? g_cnt[i] : 0;
    sh[threadIdx.x] = v;
    __syncthreads();
    for (int off = 1; off < 256; off <<= 1) {
        int u = ((int)threadIdx.x >= off) ? sh[threadIdx.x - off] : 0;
        __syncthreads();
        sh[threadIdx.x] += u;
        __syncthreads();
    }
    if (i < n) {
        int incl = sh[threadIdx.x] + g_boff[blockIdx.x];
        g_rowptr[i + 1] = incl;
        g_cursor[i]     = incl - v;
        g_inv[i]        = 1.0f / fmaxf((float)v, 1.0f);
    }
    if (blockIdx.x == 0 && threadIdx.x == 0) g_rowptr[0] = 0;
}
__global__ void fill_kernel(const int* __restrict__ ei, int E) {
    int e = blockIdx.x * blockDim.x + threadIdx.x;
    if (e < E) {
        int wide = g_wide;
        int src = wide ? ei[2 * (size_t)e]        : ei[e];
        int dst = wide ? ei[2 * ((size_t)E + e)]  : ei[(size_t)E + e];
        int pos = atomicAdd(&g_cursor[dst], 1);
        g_col[pos] = src;
    }
}

// ---------------- converter: x -> fragment-packed split-bf16 (layer 1) ----
// A blob (per m-block mb of 16 rows x k-block kb of 16 cols): 128 words.
// lane=(g,t): w0=(row g, cols 2t..2t+1), w1=(row g+8, same), w2=(row g, cols
// 8+2t..), w3=(row g+8, cols 8+2t..). Blob id = mb*8+kb.
__global__ void convert_a_kernel(const float* __restrict__ x, int n, int ntiles) {
    int id = blockIdx.x * 256 + threadIdx.x;
    if (id >= ntiles * 2048) return;
    int lane = id & 31;
    int blob = id >> 5;
    int kb = blob & 7;
    int mb = blob >> 3;
    int g = lane >> 2, t = lane & 3;
    int r0 = mb * 16 + g;
    int c0 = kb * 16 + 2 * t;

    float v[8];
    #pragma unroll
    for (int p = 0; p < 4; p++) {
        int r = r0 + (p & 1) * 8;
        int c = c0 + (p >> 1) * 8;
        float2 f = (r < n) ? *(const float2*)&x[(size_t)r * DD + c]
                           : make_float2(0.f, 0.f);
        v[2 * p] = f.x; v[2 * p + 1] = f.y;
    }
    uint32_t hi[4], lo[4];
    #pragma unroll
    for (int p = 0; p < 4; p++) {
        hi[p] = pack_bf16x2(v[2 * p], v[2 * p + 1]);
        lo[p] = pack_lo(v[2 * p], v[2 * p + 1], hi[p]);
    }
    size_t dst = (size_t)blob * 512 + lane * 16;
    *(uint4*)(g_ahi + dst) = make_uint4(hi[0], hi[1], hi[2], hi[3]);
    *(uint4*)(g_alo + dst) = make_uint4(lo[0], lo[1], lo[2], lo[3]);
}

// W blob (per n-block nb of 8 cols x k-block kb): 64 words.
__global__ void convert_w_kernel(const float* __restrict__ W0, const float* __restrict__ W1,
                                 const float* __restrict__ W2, const float* __restrict__ W3,
                                 const float* __restrict__ W4, const float* __restrict__ W5) {
    int m = blockIdx.x;
    const float* W = (m == 0) ? W0 : (m == 1) ? W1 : (m == 2) ? W2
                   : (m == 3) ? W3 : (m == 4) ? W4 : W5;
    int id = blockIdx.y * 256 + threadIdx.x;
    int lane = id & 31;
    int blob = id >> 5;
    int kb = blob & 7;
    int nb = blob >> 3;
    int g = lane >> 2, t = lane & 3;
    int nrow = nb * 8 + g;
    int c0 = kb * 16 + 2 * t;

    float2 f0 = *(const float2*)&W[nrow * DD + c0];
    float2 f1 = *(const float2*)&W[nrow * DD + c0 + 8];
    uint32_t h0 = pack_bf16x2(f0.x, f0.y);
    uint32_t h1 = pack_bf16x2(f1.x, f1.y);
    uint32_t l0 = pack_lo(f0.x, f0.y, h0);
    uint32_t l1 = pack_lo(f1.x, f1.y, h1);
    size_t dst = (size_t)m * 32768 + (size_t)blob * 256 + lane * 8;
    *(uint2*)(g_wbhi + dst) = make_uint2(h0, h1);
    *(uint2*)(g_wblo + dst) = make_uint2(l0, l1);
}

// ---------------- split-bf16 mma.sync dual GEMM (packed operands) ---------
// grid.y=0: t (fp16) ; grid.y=1: g_z = A@Wr^T + b (fp32).
__global__ __launch_bounds__(256, 1)
void gemm_mma_kernel(const float* __restrict__ bias, int layer, int n)
{
    const int tid  = threadIdx.x;
    const int wid  = tid >> 5, lane = tid & 31;
    const int gid  = lane >> 2, tig = lane & 3;
    const int warpM = wid >> 2, warpN = wid & 3;
    const int row0 = blockIdx.x * 128 + warpM * 64;
    const int mb0  = row0 >> 4;
    const int nb0  = warpN * 4;
    const int half = blockIdx.y;
    const int widx = 2 * layer + half;

    const uint4* Ahi = (const uint4*)g_ahi;
    const uint4* Alo = (const uint4*)g_alo;
    const uint2* Bhi = (const uint2*)(g_wbhi + (size_t)widx * 32768);
    const uint2* Blo = (const uint2*)(g_wblo + (size_t)widx * 32768);

    float acc[4][4][4];
    #pragma unroll
    for (int mi = 0; mi < 4; mi++)
        #pragma unroll
        for (int ni = 0; ni < 4; ni++)
            acc[mi][ni][0] = acc[mi][ni][1] = acc[mi][ni][2] = acc[mi][ni][3] = 0.f;

    #pragma unroll 2
    for (int kb = 0; kb < 8; kb++) {
        uint4 ah[4], al[4];
        uint2 bh[4], bl[4];
        #pragma unroll
        for (int mi = 0; mi < 4; mi++) {
            int bidx = ((mb0 + mi) * 8 + kb) * 32 + lane;
            ah[mi] = Ahi[bidx];
            al[mi] = Alo[bidx];
        }
        #pragma unroll
        for (int ni = 0; ni < 4; ni++) {
            int bidx = ((nb0 + ni) * 8 + kb) * 32 + lane;
            bh[ni] = Bhi[bidx];
            bl[ni] = Blo[bidx];
        }
        #pragma unroll
        for (int mi = 0; mi < 4; mi++)
            #pragma unroll
            for (int ni = 0; ni < 4; ni++) {
                MMA(acc[mi][ni], (&ah[mi].x), (&bh[ni].x));
                MMA(acc[mi][ni], (&ah[mi].x), (&bl[ni].x));
                MMA(acc[mi][ni], (&al[mi].x), (&bh[ni].x));
            }
    }

    // epilogue
    if (half) {
        #pragma unroll
        for (int ni = 0; ni < 4; ni++) {
            int col = warpN * 32 + ni * 8 + 2 * tig;
            float2 bv = *(const float2*)&bias[col];
            #pragma unroll
            for (int mi = 0; mi < 4; mi++) {
                int r0 = row0 + mi * 16 + gid;
                if (r0 < n)
                    *(float2*)&g_z[(size_t)r0 * DD + col] =
                        make_float2(acc[mi][ni][0] + bv.x, acc[mi][ni][1] + bv.y);
                if (r0 + 8 < n)
                    *(float2*)&g_z[(size_t)(r0 + 8) * DD + col] =
                        make_float2(acc[mi][ni][2] + bv.x, acc[mi][ni][3] + bv.y);
            }
        }
    } else {
        __half2* th = (__half2*)g_t;   // row pitch 64 half2
        #pragma unroll
        for (int ni = 0; ni < 4; ni++) {
            int col2 = (warpN * 32 + ni * 8 + 2 * tig) >> 1;
            #pragma unroll
            for (int mi = 0; mi < 4; mi++) {
                int r0 = row0 + mi * 16 + gid;
                if (r0 < n)
                    th[(size_t)r0 * 64 + col2] =
                        __floats2half2_rn(acc[mi][ni][0], acc[mi][ni][1]);
                if (r0 + 8 < n)
                    th[(size_t)(r0 + 8) * 64 + col2] =
                        __floats2half2_rn(acc[mi][ni][2], acc[mi][ni][3]);
            }
        }
    }
}

// ---------------- aggregate + finalize -------------------------------------
// o = [relu](mean_agg(t_fp16) + z). MODE 0: write next-layer A blobs (relu).
// MODE 1: write fp32 out (no relu).
template <int MODE>
__global__ void aggregate_kernel(float* __restrict__ out, int n)
{
    int node = (blockIdx.x * blockDim.x + threadIdx.x) >> 5;
    int lane = threadIdx.x & 31;
    if (node >= n) return;

    int beg = g_rowptr[node];
    int end = g_rowptr[node + 1];
    const uint2* t2 = (const uint2*)g_t;   // row = 32 uint2 (128 half)

    float4 acc = make_float4(0.f, 0.f, 0.f, 0.f);
    int j = beg;
    for (; j + 4 <= end; j += 4) {
        int s0 = g_col[j], s1 = g_col[j + 1], s2 = g_col[j + 2], s3 = g_col[j + 3];
        uint2 p0 = t2[(size_t)s0 * 32 + lane];
        uint2 p1 = t2[(size_t)s1 * 32 + lane];
        uint2 p2 = t2[(size_t)s2 * 32 + lane];
        uint2 p3 = t2[(size_t)s3 * 32 + lane];
        float2 a0 = __half22float2(*(__half2*)&p0.x), b0 = __half22float2(*(__half2*)&p0.y);
        float2 a1 = __half22float2(*(__half2*)&p1.x), b1 = __half22float2(*(__half2*)&p1.y);
        float2 a2 = __half22float2(*(__half2*)&p2.x), b2 = __half22float2(*(__half2*)&p2.y);
        float2 a3 = __half22float2(*(__half2*)&p3.x), b3 = __half22float2(*(__half2*)&p3.y);
        acc.x += (a0.x + a1.x) + (a2.x + a3.x);
        acc.y += (a0.y + a1.y) + (a2.y + a3.y);
        acc.z += (b0.x + b1.x) + (b2.x + b3.x);
        acc.w += (b0.y + b1.y) + (b2.y + b3.y);
    }
    for (; j < end; j++) {
        int s = g_col[j];
        uint2 p = t2[(size_t)s * 32 + lane];
        float2 a = __half22float2(*(__half2*)&p.x), b = __half22float2(*(__half2*)&p.y);
        acc.x += a.x; acc.y += a.y; acc.z += b.x; acc.w += b.y;
    }

    float inv = g_inv[node];
    float4 z = ((const float4*)g_z)[(size_t)node * 32 + lane];
    float4 o;
    o.x = fmaf(acc.x, inv, z.x);
    o.y = fmaf(acc.y, inv, z.y);
    o.z = fmaf(acc.z, inv, z.z);
    o.w = fmaf(acc.w, inv, z.w);

    if (MODE == 1) {
        ((float4*)out)[(size_t)node * 32 + lane] = o;
    } else {
        o.x = fmaxf(o.x, 0.f); o.y = fmaxf(o.y, 0.f);
        o.z = fmaxf(o.z, 0.f); o.w = fmaxf(o.w, 0.f);
        // write fragment-packed split-bf16 blob words for next layer's A
        int rm = node & 15;
        int mb = node >> 4;
        int wb = (rm < 8) ? 0 : 1;
        int g  = (rm < 8) ? rm : rm - 8;
        int c  = 4 * lane;
        int kb = c >> 4;
        int jj = c & 15;                       // 0,4,8,12
        int t1 = (jj < 8) ? (jj >> 1) : ((jj - 8) >> 1);
        int w1 = wb + ((jj < 8) ? 0 : 2);
        int j2 = jj + 2;
        int t2i = (j2 < 8) ? (j2 >> 1) : ((j2 - 8) >> 1);
        int w2 = wb + ((j2 < 8) ? 0 : 2);

        uint32_t hi1 = pack_bf16x2(o.x, o.y);
        uint32_t lo1 = pack_lo(o.x, o.y, hi1);
        uint32_t hi2 = pack_bf16x2(o.z, o.w);
        uint32_t lo2 = pack_lo(o.z, o.w, hi2);

        uint32_t* AH = (uint32_t*)g_ahi;
        uint32_t* AL = (uint32_t*)g_alo;
        size_t base = (size_t)(mb * 8 + kb) * 128;
        AH[base + (g * 4 + t1) * 4 + w1] = hi1;
        AL[base + (g * 4 + t1) * 4 + w1] = lo1;
        AH[base + (g * 4 + t2i) * 4 + w2] = hi2;
        AL[base + (g * 4 + t2i) * 4 + w2] = lo2;
    }
}

// ---------------- launch ----------------
extern "C" void kernel_launch(void* const* d_in, const int* in_sizes, int n_in,
                              void* d_out, int out_size)
{
    const float* x   = (const float*)d_in[0];
    const int*   ei  = (const int*)d_in[1];
    const float* Wl1 = (const float*)d_in[2];
    const float* Wr1 = (const float*)d_in[3];
    const float* b1  = (const float*)d_in[4];
    const float* Wl2 = (const float*)d_in[5];
    const float* Wr2 = (const float*)d_in[6];
    const float* b2  = (const float*)d_in[7];
    const float* Wl3 = (const float*)d_in[8];
    const float* Wr3 = (const float*)d_in[9];
    const float* b3  = (const float*)d_in[10];
    float* out = (float*)d_out;

    const int N = in_sizes[0] / DD;
    const int E = in_sizes[1] / 2;
    const int nb = (N + 255) / 256;
    const int ntiles = (N + 127) / 128;

    // ---- edge dtype detection + CSR ----
    init_flag_kernel<<<1, 1>>>();
    detect_kernel<<<256, 256>>>(ei, E);
    zero_cnt_kernel<<<nb, 256>>>(N);
    hist_kernel<<<(E + 255) / 256, 256>>>(ei, E);
    scan1_kernel<<<nb, 256>>>(N);
    scan2_kernel<<<1, 1024>>>(nb);
    scan3_kernel<<<nb, 256>>>(N);
    fill_kernel<<<(E + 255) / 256, 256>>>(ei, E);

    // ---- weights -> fragment-packed split-bf16 ----
    convert_w_kernel<<<dim3(6, 16), 256>>>(Wl1, Wr1, Wl2, Wr2, Wl3, Wr3);

    const int cgrid = ntiles * 8;
    dim3 ggrid(ntiles, 2);
    const int agg_grid = (N + 7) / 8;

    // ---- layer 1 ----
    convert_a_kernel<<<cgrid, 256>>>(x, N, ntiles);
    gemm_mma_kernel<<<ggrid, 256>>>(b1, 0, N);
    aggregate_kernel<0><<<agg_grid, 256>>>(out, N);
    // ---- layer 2 (A blobs written by aggregate) ----
    gemm_mma_kernel<<<ggrid, 256>>>(b2, 1, N);
    aggregate_kernel<0><<<agg_grid, 256>>>(out, N);
    // ---- layer 3 ----
    gemm_mma_kernel<<<ggrid, 256>>>(b3, 2, N);
    aggregate_kernel<1><<<agg_grid, 256>>>(out, N);
}